// round 2
// baseline (speedup 1.0000x reference)
#include <cuda_runtime.h>
#include <cuda_bf16.h>
#include <math.h>

// ---------------------------------------------------------------------------
// TrackMPNN forward, fp32.
// Inputs (metadata order):
//  0 x[Nnew,64] 1 h_in[Nold,64]
//  2 node_rows 3 node_cols 4 node_vals (nnz_n)
//  5 edge_rows 6 edge_cols 7 edge_vals (nnz_e)
//  8 W1[64,64] 9 b1[64] 10 gamma[64] 11 beta[64] 12 W2[64,64] 13 b2[64]
// 14 Wi_n[192,64] 15 bi_n 16 Wh_n 17 bh_n
// 18 Wi_e 19 bi_e 20 Wh_e 21 bh_e
// 22 w_on[64] 23 b_on[1] 24 w_oe[64] 25 b_oe[1]
// Output: concat( sigmoid(y)[N], y[N], h_out[N,64] ) as float32.
// ---------------------------------------------------------------------------

#define NH 64
#define MAXN      400000
#define MAXNEW    100000

// -------- device scratch (no allocations allowed) --------
__device__ float g_dn[MAXN];
__device__ float g_de[MAXN];
__device__ float g_h [(size_t)MAXN * NH];
__device__ float g_mn[(size_t)MAXN * NH];
__device__ float g_me[(size_t)MAXN * NH];
__device__ float g_t1[(size_t)MAXNEW * NH];
__device__ float g_sum[NH], g_sumsq[NH], g_a[NH], g_bsh[NH];

// ---------------------------------------------------------------------------
// prep: zero m_n/m_e/dn/de/sums, copy h_in into top of h
// ---------------------------------------------------------------------------
__global__ void prep_kernel(const float* __restrict__ h_in, int N, int Nold) {
    size_t i = (size_t)blockIdx.x * blockDim.x + threadIdx.x;
    size_t stride = (size_t)gridDim.x * blockDim.x;
    float4 z4 = make_float4(0.f, 0.f, 0.f, 0.f);
    float4* mn4 = reinterpret_cast<float4*>(g_mn);
    float4* me4 = reinterpret_cast<float4*>(g_me);
    size_t n4 = (size_t)N * (NH / 4);
    for (size_t idx = i; idx < n4; idx += stride) { mn4[idx] = z4; me4[idx] = z4; }
    for (size_t idx = i; idx < (size_t)N; idx += stride) { g_dn[idx] = 0.f; g_de[idx] = 0.f; }
    if (i < NH) { g_sum[i] = 0.f; g_sumsq[i] = 0.f; }
    const float4* hin4 = reinterpret_cast<const float4*>(h_in);
    float4* h4 = reinterpret_cast<float4*>(g_h);
    size_t c4 = (size_t)Nold * (NH / 4);
    for (size_t idx = i; idx < c4; idx += stride) h4[idx] = hin4[idx];
}

// ---------------------------------------------------------------------------
// diagonal extraction: d[r] += vals[i] where rows[i]==cols[i]
// ---------------------------------------------------------------------------
__global__ void diag_kernel(const int* __restrict__ rows, const int* __restrict__ cols,
                            const float* __restrict__ vals, int nnz, int which) {
    float* d = which ? g_de : g_dn;
    int i = blockIdx.x * blockDim.x + threadIdx.x;
    int stride = gridDim.x * blockDim.x;
    for (int e = i; e < nnz; e += stride) {
        int r = rows[e];
        if (r == cols[e]) atomicAdd(&d[r], vals[e]);
    }
}

// ---------------------------------------------------------------------------
// t1 = x @ W1^T + b1, plus per-column sum / sumsq for BN stats
// block: 256 threads, 64-row tile. thread = (rgroup in [0,4), col in [0,64)),
// each thread owns 16 rows of one output column.
// ---------------------------------------------------------------------------
__global__ void t1_kernel(const float* __restrict__ x, const float* __restrict__ W1,
                          const float* __restrict__ b1, int Nnew) {
    __shared__ float sW[64 * 65];
    __shared__ float sX[64 * 64];
    __shared__ float sS[256];
    __shared__ float sS2[256];
    int tid = threadIdx.x;
    int c = tid & 63, rg = tid >> 6;
    for (int idx = tid; idx < 64 * 64; idx += 256) {
        int j = idx >> 6, k = idx & 63;
        sW[j * 65 + k] = W1[idx];
    }
    int base = blockIdx.x * 64;
    for (int idx = tid; idx < 64 * 64; idx += 256) {
        int r = idx >> 6, k = idx & 63;
        int gr = base + r;
        sX[idx] = (gr < Nnew) ? x[(size_t)gr * 64 + k] : 0.f;
    }
    __syncthreads();
    float acc[16];
    float bb = b1[c];
#pragma unroll
    for (int i = 0; i < 16; i++) acc[i] = bb;
#pragma unroll 4
    for (int k = 0; k < 64; k++) {
        float w = sW[c * 65 + k];
#pragma unroll
        for (int i = 0; i < 16; i++) acc[i] += w * sX[(rg * 16 + i) * 64 + k];
    }
    float s = 0.f, s2 = 0.f;
#pragma unroll
    for (int i = 0; i < 16; i++) {
        int gr = base + rg * 16 + i;
        if (gr < Nnew) {
            g_t1[(size_t)gr * 64 + c] = acc[i];
            s += acc[i];
            s2 += acc[i] * acc[i];
        }
    }
    sS[tid] = s; sS2[tid] = s2;
    __syncthreads();
    if (tid < 64) {
        float ts = 0.f, ts2 = 0.f;
#pragma unroll
        for (int g = 0; g < 4; g++) { ts += sS[g * 64 + tid]; ts2 += sS2[g * 64 + tid]; }
        atomicAdd(&g_sum[tid], ts);
        atomicAdd(&g_sumsq[tid], ts2);
    }
}

// ---------------------------------------------------------------------------
// BN stats -> affine coefficients:  a = gamma*rsqrt(var+eps), bsh = beta - mu*a
// ---------------------------------------------------------------------------
__global__ void stats_kernel(const float* __restrict__ gamma, const float* __restrict__ beta,
                             int Nnew) {
    int c = threadIdx.x;
    float invN = 1.f / (float)Nnew;
    float mu = g_sum[c] * invN;
    float var = g_sumsq[c] * invN - mu * mu;
    float a = gamma[c] * rsqrtf(var + 1e-5f);
    g_a[c] = a;
    g_bsh[c] = beta[c] - mu * a;
}

// ---------------------------------------------------------------------------
// t2 = relu(bn(t1)) @ W2^T + b2 ; h[Nold+r] = dn[Nold+r] * t2[r]
// ---------------------------------------------------------------------------
__global__ void t2_kernel(const float* __restrict__ W2, const float* __restrict__ b2,
                          int Nnew, int Nold) {
    __shared__ float sW[64 * 65];
    __shared__ float sX[64 * 64];
    __shared__ float sA[64], sB[64];
    int tid = threadIdx.x;
    int c = tid & 63, rg = tid >> 6;
    if (tid < 64) { sA[tid] = g_a[tid]; sB[tid] = g_bsh[tid]; }
    for (int idx = tid; idx < 64 * 64; idx += 256) {
        int j = idx >> 6, k = idx & 63;
        sW[j * 65 + k] = W2[idx];
    }
    __syncthreads();
    int base = blockIdx.x * 64;
    for (int idx = tid; idx < 64 * 64; idx += 256) {
        int r = idx >> 6, k = idx & 63;
        int gr = base + r;
        float v = 0.f;
        if (gr < Nnew) v = fmaxf(fmaf(g_t1[(size_t)gr * 64 + k], sA[k], sB[k]), 0.f);
        sX[idx] = v;
    }
    __syncthreads();
    float acc[16];
    float bb = b2[c];
#pragma unroll
    for (int i = 0; i < 16; i++) acc[i] = bb;
#pragma unroll 4
    for (int k = 0; k < 64; k++) {
        float w = sW[c * 65 + k];
#pragma unroll
        for (int i = 0; i < 16; i++) acc[i] += w * sX[(rg * 16 + i) * 64 + k];
    }
#pragma unroll
    for (int i = 0; i < 16; i++) {
        int gr = base + rg * 16 + i;
        if (gr < Nnew) {
            int hr = Nold + gr;
            g_h[(size_t)hr * 64 + c] = g_dn[hr] * acc[i];
        }
    }
}

// ---------------------------------------------------------------------------
// SpMM: m[row] += val * h[col] for off-diagonal entries. warp per entry.
// ---------------------------------------------------------------------------
__global__ void spmm_kernel(const int* __restrict__ rows, const int* __restrict__ cols,
                            const float* __restrict__ vals, int nnz, int which) {
    float* m = which ? g_me : g_mn;
    int gw = (blockIdx.x * blockDim.x + threadIdx.x) >> 5;
    int lane = threadIdx.x & 31;
    int nw = (gridDim.x * blockDim.x) >> 5;
    for (int e = gw; e < nnz; e += nw) {
        int r = rows[e], cc = cols[e];
        if (r == cc) continue;
        float v = vals[e];
        float2 hv = *reinterpret_cast<const float2*>(g_h + (size_t)cc * 64 + lane * 2);
        float* mp = m + (size_t)r * 64 + lane * 2;
        atomicAdd(mp,     v * hv.x);
        atomicAdd(mp + 1, v * hv.y);
    }
}

// ---------------------------------------------------------------------------
// fused GRU (node + edge) + masking + output heads
// One persistent block per SM; all 4 weight matrices in smem (192x65 padded).
// Thread = (rgroup in [0,4), col in [0,64)), owns 8 rows x 1 col x 6 gates.
// ---------------------------------------------------------------------------
#define SW_STRIDE 65
#define OFF_WIN 0
#define OFF_WHN (192 * SW_STRIDE)
#define OFF_WIE (2 * 192 * SW_STRIDE)
#define OFF_WHE (3 * 192 * SW_STRIDE)
#define OFF_BIN (4 * 192 * SW_STRIDE)
#define OFF_BHN (OFF_BIN + 192)
#define OFF_BIE (OFF_BHN + 192)
#define OFF_BHE (OFF_BIE + 192)
#define OFF_M   (OFF_BHE + 192)
#define OFF_H   (OFF_M + 32 * 64)
#define OFF_E   (OFF_H + 32 * 64)
#define OFF_Y   (OFF_E + 32 * 64)
#define SMEM_FLOATS (OFF_Y + 64)
#define SMEM_BYTES  (SMEM_FLOATS * 4)

__device__ __forceinline__ float sigmoidf_(float v) { return 1.f / (1.f + __expf(-v)); }

__device__ __forceinline__ void gru_pass(const float* __restrict__ sWi, const float* __restrict__ sWh,
                                         const float* __restrict__ sBi, const float* __restrict__ sBh,
                                         const float* __restrict__ sIn, const float* __restrict__ sHh,
                                         int r0, int c, float* hout) {
    float air[8], aiz[8], ain[8], ahr[8], ahz[8], ahn[8];
    float bir = sBi[c], biz = sBi[64 + c], bin = sBi[128 + c];
    float bhr = sBh[c], bhz = sBh[64 + c], bhn = sBh[128 + c];
#pragma unroll
    for (int i = 0; i < 8; i++) {
        air[i] = bir; aiz[i] = biz; ain[i] = bin;
        ahr[i] = bhr; ahz[i] = bhz; ahn[i] = bhn;
    }
#pragma unroll 4
    for (int k = 0; k < 64; k++) {
        float wir = sWi[c * SW_STRIDE + k];
        float wiz = sWi[(64 + c) * SW_STRIDE + k];
        float win = sWi[(128 + c) * SW_STRIDE + k];
        float whr = sWh[c * SW_STRIDE + k];
        float whz = sWh[(64 + c) * SW_STRIDE + k];
        float whn = sWh[(128 + c) * SW_STRIDE + k];
#pragma unroll
        for (int i = 0; i < 8; i++) {
            float m = sIn[(r0 + i) * 64 + k];
            float hh = sHh[(r0 + i) * 64 + k];
            air[i] += wir * m; aiz[i] += wiz * m; ain[i] += win * m;
            ahr[i] += whr * hh; ahz[i] += whz * hh; ahn[i] += whn * hh;
        }
    }
#pragma unroll
    for (int i = 0; i < 8; i++) {
        float rr = sigmoidf_(air[i] + ahr[i]);
        float zz = sigmoidf_(aiz[i] + ahz[i]);
        float ng = tanhf(ain[i] + rr * ahn[i]);
        hout[i] = (1.f - zz) * ng + zz * sHh[(r0 + i) * 64 + c];
    }
}

__global__ void __launch_bounds__(256, 1)
gru_kernel(const float* __restrict__ Wi_n, const float* __restrict__ bi_n,
           const float* __restrict__ Wh_n, const float* __restrict__ bh_n,
           const float* __restrict__ Wi_e, const float* __restrict__ bi_e,
           const float* __restrict__ Wh_e, const float* __restrict__ bh_e,
           const float* __restrict__ w_on, const float* __restrict__ b_on,
           const float* __restrict__ w_oe, const float* __restrict__ b_oe,
           float* __restrict__ out, int N) {
    extern __shared__ float sm[];
    float* sWiN = sm + OFF_WIN;
    float* sWhN = sm + OFF_WHN;
    float* sWiE = sm + OFF_WIE;
    float* sWhE = sm + OFF_WHE;
    float* sBiN = sm + OFF_BIN;
    float* sBhN = sm + OFF_BHN;
    float* sBiE = sm + OFF_BIE;
    float* sBhE = sm + OFF_BHE;
    float* sM = sm + OFF_M;
    float* sH = sm + OFF_H;
    float* sE = sm + OFF_E;
    float* sY = sm + OFF_Y;

    int tid = threadIdx.x;
    int c = tid & 63, rg = tid >> 6;
    int lane = tid & 31, warp = tid >> 5;

    for (int idx = tid; idx < 192 * 64; idx += 256) {
        int j = idx >> 6, k = idx & 63;
        int p = j * SW_STRIDE + k;
        sWiN[p] = Wi_n[idx];
        sWhN[p] = Wh_n[idx];
        sWiE[p] = Wi_e[idx];
        sWhE[p] = Wh_e[idx];
    }
    if (tid < 192) {
        sBiN[tid] = bi_n[tid]; sBhN[tid] = bh_n[tid];
        sBiE[tid] = bi_e[tid]; sBhE[tid] = bh_e[tid];
    }
    float won = w_on[c], woe = w_oe[c];
    float bon = b_on[0], boe = b_oe[0];

    float* outS = out;
    float* outY = out + N;
    float* outH = out + 2 * (size_t)N;

    int ntiles = (N + 31) / 32;
    for (int t = blockIdx.x; t < ntiles; t += gridDim.x) {
        int base = t * 32;
        __syncthreads();  // protect sM/sH/sE/sY from previous tile
        for (int idx = tid; idx < 32 * 64; idx += 256) {
            int r = idx >> 6, k = idx & 63;
            int gr = base + r;
            bool ok = gr < N;
            size_t off = (size_t)gr * 64 + k;
            sM[idx] = ok ? g_mn[off] : 0.f;
            sH[idx] = ok ? g_h[off] : 0.f;
            sE[idx] = ok ? g_me[off] : 0.f;
        }
        __syncthreads();

        int r0 = rg * 8;
        float hnode[8], hedge[8];
        gru_pass(sWiN, sWhN, sBiN, sBhN, sM, sH, r0, c, hnode);
        gru_pass(sWiE, sWhE, sBiE, sBhE, sE, sH, r0, c, hedge);

        float yp[8];
#pragma unroll
        for (int i = 0; i < 8; i++) {
            int gr = base + r0 + i;
            float dnv = 0.f, dev = 0.f;
            if (gr < N) { dnv = g_dn[gr]; dev = g_de[gr]; }
            float ho = dnv * hnode[i] + dev * hedge[i];
            if (gr < N) outH[(size_t)gr * 64 + c] = ho;
            yp[i] = ho * (dnv * won + dev * woe);
        }
#pragma unroll
        for (int i = 0; i < 8; i++) {
#pragma unroll
            for (int o = 16; o > 0; o >>= 1)
                yp[i] += __shfl_xor_sync(0xffffffffu, yp[i], o);
        }
        if (lane == 0) {
#pragma unroll
            for (int i = 0; i < 8; i++) sY[warp * 8 + i] = yp[i];
        }
        __syncthreads();
        if (tid < 32) {
            int gr = base + tid;
            if (gr < N) {
                int g2 = tid >> 3, i = tid & 7;
                float v = sY[(2 * g2) * 8 + i] + sY[(2 * g2 + 1) * 8 + i];
                float dnv = g_dn[gr], dev = g_de[gr];
                float yv = v + dnv * bon + dev * boe;
                outY[gr] = yv;
                outS[gr] = sigmoidf_(yv);
            }
        }
    }
}

// ---------------------------------------------------------------------------
extern "C" void kernel_launch(void* const* d_in, const int* in_sizes, int n_in,
                              void* d_out, int out_size) {
    const float* x     = (const float*)d_in[0];
    const float* h_in  = (const float*)d_in[1];
    const int*   nrows = (const int*)d_in[2];
    const int*   ncols = (const int*)d_in[3];
    const float* nvals = (const float*)d_in[4];
    const int*   erows = (const int*)d_in[5];
    const int*   ecols = (const int*)d_in[6];
    const float* evals = (const float*)d_in[7];
    const float* W1    = (const float*)d_in[8];
    const float* b1    = (const float*)d_in[9];
    const float* gamma = (const float*)d_in[10];
    const float* beta  = (const float*)d_in[11];
    const float* W2    = (const float*)d_in[12];
    const float* b2    = (const float*)d_in[13];
    const float* Wi_n  = (const float*)d_in[14];
    const float* bi_n  = (const float*)d_in[15];
    const float* Wh_n  = (const float*)d_in[16];
    const float* bh_n  = (const float*)d_in[17];
    const float* Wi_e  = (const float*)d_in[18];
    const float* bi_e  = (const float*)d_in[19];
    const float* Wh_e  = (const float*)d_in[20];
    const float* bh_e  = (const float*)d_in[21];
    const float* w_on  = (const float*)d_in[22];
    const float* b_on  = (const float*)d_in[23];
    const float* w_oe  = (const float*)d_in[24];
    const float* b_oe  = (const float*)d_in[25];

    int Nnew = in_sizes[0] / NH;
    int Nold = in_sizes[1] / NH;
    int N = Nnew + Nold;
    int nnz_n = in_sizes[2];
    int nnz_e = in_sizes[5];
    if (N > MAXN || Nnew > MAXNEW) return;

    float* out = (float*)d_out;

    cudaFuncSetAttribute(gru_kernel, cudaFuncAttributeMaxDynamicSharedMemorySize, SMEM_BYTES);

    // 1. zero scratch + copy h_in
    prep_kernel<<<2048, 256>>>(h_in, N, Nold);
    // 2. diagonal extraction
    diag_kernel<<<1024, 256>>>(nrows, ncols, nvals, nnz_n, 0);
    diag_kernel<<<1024, 256>>>(erows, ecols, evals, nnz_e, 1);
    // 3. input transform
    int tblocks = (Nnew + 63) / 64;
    t1_kernel<<<tblocks, 256>>>(x, W1, b1, Nnew);
    stats_kernel<<<1, 64>>>(gamma, beta, Nnew);
    t2_kernel<<<tblocks, 256>>>(W2, b2, Nnew, Nold);
    // 4. sparse message passing
    spmm_kernel<<<4096, 256>>>(nrows, ncols, nvals, nnz_n, 0);
    spmm_kernel<<<4096, 256>>>(erows, ecols, evals, nnz_e, 1);
    // 5. fused GRU + masking + heads
    gru_kernel<<<148, 256, SMEM_BYTES>>>(Wi_n, bi_n, Wh_n, bh_n,
                                         Wi_e, bi_e, Wh_e, bh_e,
                                         w_on, b_on, w_oe, b_oe, out, N);
    (void)n_in; (void)out_size;
}

// round 3
// speedup vs baseline: 1.1451x; 1.1451x over previous
#include <cuda_runtime.h>
#include <cuda_bf16.h>
#include <math.h>
#include <stdint.h>

// ---------------------------------------------------------------------------
// TrackMPNN forward, fp32.
// Output: concat( sigmoid(y)[N], y[N], h_out[N,64] ) as float32.
// ---------------------------------------------------------------------------

#define NH 64
#define MAXN      400000
#define MAXNEW    100000

// -------- device scratch (no allocations allowed) --------
__device__ float g_dn[MAXN];
__device__ float g_de[MAXN];
__device__ float g_h [(size_t)MAXN * NH];
__device__ float g_mn[(size_t)MAXN * NH];
__device__ float g_me[(size_t)MAXN * NH];
__device__ float g_t1[(size_t)MAXNEW * NH];
__device__ float g_sum[NH], g_sumsq[NH], g_a[NH], g_bsh[NH];

// ---------------------------------------------------------------------------
// f32x2 packed FMA helpers (Blackwell)
// ---------------------------------------------------------------------------
__device__ __forceinline__ uint64_t fma2_(uint64_t a, uint64_t b, uint64_t c) {
    uint64_t d;
    asm("fma.rn.f32x2 %0, %1, %2, %3;" : "=l"(d) : "l"(a), "l"(b), "l"(c));
    return d;
}
__device__ __forceinline__ float hsum2_(uint64_t v) {
    float lo = __uint_as_float((unsigned)(v & 0xffffffffu));
    float hi = __uint_as_float((unsigned)(v >> 32));
    return lo + hi;
}
__device__ __forceinline__ float sigmoidf_(float v) { return 1.f / (1.f + __expf(-v)); }

// ---------------------------------------------------------------------------
// prep: zero m_n/m_e/dn/de/sums, copy h_in into top of h
// ---------------------------------------------------------------------------
__global__ void prep_kernel(const float* __restrict__ h_in, int N, int Nold) {
    size_t i = (size_t)blockIdx.x * blockDim.x + threadIdx.x;
    size_t stride = (size_t)gridDim.x * blockDim.x;
    float4 z4 = make_float4(0.f, 0.f, 0.f, 0.f);
    float4* mn4 = reinterpret_cast<float4*>(g_mn);
    float4* me4 = reinterpret_cast<float4*>(g_me);
    size_t n4 = (size_t)N * (NH / 4);
    for (size_t idx = i; idx < n4; idx += stride) { mn4[idx] = z4; me4[idx] = z4; }
    for (size_t idx = i; idx < (size_t)N; idx += stride) { g_dn[idx] = 0.f; g_de[idx] = 0.f; }
    if (i < NH) { g_sum[i] = 0.f; g_sumsq[i] = 0.f; }
    const float4* hin4 = reinterpret_cast<const float4*>(h_in);
    float4* h4 = reinterpret_cast<float4*>(g_h);
    size_t c4 = (size_t)Nold * (NH / 4);
    for (size_t idx = i; idx < c4; idx += stride) h4[idx] = hin4[idx];
}

// ---------------------------------------------------------------------------
// diagonal extraction
// ---------------------------------------------------------------------------
__global__ void diag_kernel(const int* __restrict__ rows, const int* __restrict__ cols,
                            const float* __restrict__ vals, int nnz, int which) {
    float* d = which ? g_de : g_dn;
    int i = blockIdx.x * blockDim.x + threadIdx.x;
    int stride = gridDim.x * blockDim.x;
    for (int e = i; e < nnz; e += stride) {
        int r = rows[e];
        if (r == cols[e]) atomicAdd(&d[r], vals[e]);
    }
}

// ---------------------------------------------------------------------------
// t1 = x @ W1^T + b1, plus per-column sum / sumsq for BN stats.
// 32-row tile, 256 threads: thread = (rgroup in [0,4), col in [0,64)),
// owns 8 rows of one output column. Low regs -> high occupancy.
// ---------------------------------------------------------------------------
__global__ void t1_kernel(const float* __restrict__ x, const float* __restrict__ W1,
                          const float* __restrict__ b1, int Nnew) {
    __shared__ float sW[64 * 65];
    __shared__ float sX[32 * 64];
    __shared__ float sS[256];
    __shared__ float sS2[256];
    int tid = threadIdx.x;
    int c = tid & 63, rg = tid >> 6;
    for (int idx = tid; idx < 64 * 64; idx += 256) {
        int j = idx >> 6, k = idx & 63;
        sW[j * 65 + k] = W1[idx];
    }
    int base = blockIdx.x * 32;
    for (int idx = tid; idx < 32 * 16; idx += 256) {
        int r = idx >> 4, k4 = idx & 15;
        int gr = base + r;
        float4 v = make_float4(0.f, 0.f, 0.f, 0.f);
        if (gr < Nnew) v = reinterpret_cast<const float4*>(x)[(size_t)gr * 16 + k4];
        reinterpret_cast<float4*>(sX)[idx] = v;
    }
    __syncthreads();
    float acc[8];
    float bb = b1[c];
#pragma unroll
    for (int i = 0; i < 8; i++) acc[i] = bb;
#pragma unroll 4
    for (int k = 0; k < 64; k++) {
        float w = sW[c * 65 + k];
#pragma unroll
        for (int i = 0; i < 8; i++) acc[i] += w * sX[(rg * 8 + i) * 64 + k];
    }
    float s = 0.f, s2 = 0.f;
#pragma unroll
    for (int i = 0; i < 8; i++) {
        int gr = base + rg * 8 + i;
        if (gr < Nnew) {
            g_t1[(size_t)gr * 64 + c] = acc[i];
            s += acc[i];
            s2 += acc[i] * acc[i];
        }
    }
    sS[tid] = s; sS2[tid] = s2;
    __syncthreads();
    if (tid < 64) {
        float ts = 0.f, ts2 = 0.f;
#pragma unroll
        for (int g = 0; g < 4; g++) { ts += sS[g * 64 + tid]; ts2 += sS2[g * 64 + tid]; }
        atomicAdd(&g_sum[tid], ts);
        atomicAdd(&g_sumsq[tid], ts2);
    }
}

// ---------------------------------------------------------------------------
// BN stats -> affine coefficients
// ---------------------------------------------------------------------------
__global__ void stats_kernel(const float* __restrict__ gamma, const float* __restrict__ beta,
                             int Nnew) {
    int c = threadIdx.x;
    float invN = 1.f / (float)Nnew;
    float mu = g_sum[c] * invN;
    float var = g_sumsq[c] * invN - mu * mu;
    float a = gamma[c] * rsqrtf(var + 1e-5f);
    g_a[c] = a;
    g_bsh[c] = beta[c] - mu * a;
}

// ---------------------------------------------------------------------------
// t2 = relu(bn(t1)) @ W2^T + b2 ; h[Nold+r] = dn[Nold+r] * t2[r]
// ---------------------------------------------------------------------------
__global__ void t2_kernel(const float* __restrict__ W2, const float* __restrict__ b2,
                          int Nnew, int Nold) {
    __shared__ float sW[64 * 65];
    __shared__ float sX[32 * 64];
    __shared__ float sA[64], sB[64];
    int tid = threadIdx.x;
    int c = tid & 63, rg = tid >> 6;
    if (tid < 64) { sA[tid] = g_a[tid]; sB[tid] = g_bsh[tid]; }
    for (int idx = tid; idx < 64 * 64; idx += 256) {
        int j = idx >> 6, k = idx & 63;
        sW[j * 65 + k] = W2[idx];
    }
    __syncthreads();
    int base = blockIdx.x * 32;
    for (int idx = tid; idx < 32 * 64; idx += 256) {
        int r = idx >> 6, k = idx & 63;
        int gr = base + r;
        float v = 0.f;
        if (gr < Nnew) v = fmaxf(fmaf(g_t1[(size_t)gr * 64 + k], sA[k], sB[k]), 0.f);
        sX[idx] = v;
    }
    __syncthreads();
    float acc[8];
    float bb = b2[c];
#pragma unroll
    for (int i = 0; i < 8; i++) acc[i] = bb;
#pragma unroll 4
    for (int k = 0; k < 64; k++) {
        float w = sW[c * 65 + k];
#pragma unroll
        for (int i = 0; i < 8; i++) acc[i] += w * sX[(rg * 8 + i) * 64 + k];
    }
#pragma unroll
    for (int i = 0; i < 8; i++) {
        int gr = base + rg * 8 + i;
        if (gr < Nnew) {
            int hr = Nold + gr;
            g_h[(size_t)hr * 64 + c] = g_dn[hr] * acc[i];
        }
    }
}

// ---------------------------------------------------------------------------
// SpMM: m[row] += val * h[col] off-diagonal. 16 threads per edge, each thread
// handles one float4 quarter-row with a single vector red (4x fewer atomic
// instructions than scalar atomicAdd).
// ---------------------------------------------------------------------------
__global__ void spmm_kernel(const int* __restrict__ rows, const int* __restrict__ cols,
                            const float* __restrict__ vals, int nnz, int which) {
    float* m = which ? g_me : g_mn;
    long long gtid = (long long)blockIdx.x * blockDim.x + threadIdx.x;
    int q = (int)(gtid & 15);
    long long e = gtid >> 4;
    long long estride = ((long long)gridDim.x * blockDim.x) >> 4;
    for (; e < nnz; e += estride) {
        int r = rows[e], cc = cols[e];
        if (r == cc) continue;
        float v = vals[e];
        float4 hv = __ldg(reinterpret_cast<const float4*>(g_h + (size_t)cc * 64) + q);
        float* mp = m + (size_t)r * 64 + q * 4;
        asm volatile("red.global.add.v4.f32 [%0], {%1, %2, %3, %4};"
                     :: "l"(mp), "f"(v * hv.x), "f"(v * hv.y), "f"(v * hv.z), "f"(v * hv.w)
                     : "memory");
    }
}

// ---------------------------------------------------------------------------
// fused GRU (node + edge) + masking + output heads, FFMA2 (f32x2) inner loop.
// One persistent block per SM; all 4 weight matrices in smem, stride 66
// (33 8-byte granules, odd -> conflict-free LDS.64 weight loads).
// Thread = (rgroup in [0,4), col in [0,64)), owns 8 rows x 1 col x 6 gates.
// ---------------------------------------------------------------------------
#define SW_STRIDE 66
#define OFF_WIN 0
#define OFF_WHN (192 * SW_STRIDE)
#define OFF_WIE (2 * 192 * SW_STRIDE)
#define OFF_WHE (3 * 192 * SW_STRIDE)
#define OFF_BIN (4 * 192 * SW_STRIDE)
#define OFF_BHN (OFF_BIN + 192)
#define OFF_BIE (OFF_BHN + 192)
#define OFF_BHE (OFF_BIE + 192)
#define OFF_M   (OFF_BHE + 192)
#define OFF_H   (OFF_M + 32 * 64)
#define OFF_E   (OFF_H + 32 * 64)
#define OFF_Y   (OFF_E + 32 * 64)
#define SMEM_FLOATS (OFF_Y + 64)
#define SMEM_BYTES  (SMEM_FLOATS * 4)

__device__ __forceinline__ void gru_pass(const float* __restrict__ sWi, const float* __restrict__ sWh,
                                         const float* __restrict__ sBi, const float* __restrict__ sBh,
                                         const float* __restrict__ sIn, const float* __restrict__ sHh,
                                         int r0, int c, float* hout) {
    uint64_t air[8], aiz[8], ain[8], ahr[8], ahz[8], ahn[8];
#pragma unroll
    for (int i = 0; i < 8; i++) {
        air[i] = 0ull; aiz[i] = 0ull; ain[i] = 0ull;
        ahr[i] = 0ull; ahz[i] = 0ull; ahn[i] = 0ull;
    }
#pragma unroll 2
    for (int k = 0; k < 64; k += 2) {
        uint64_t wir = *reinterpret_cast<const uint64_t*>(&sWi[c * SW_STRIDE + k]);
        uint64_t wiz = *reinterpret_cast<const uint64_t*>(&sWi[(64 + c) * SW_STRIDE + k]);
        uint64_t win = *reinterpret_cast<const uint64_t*>(&sWi[(128 + c) * SW_STRIDE + k]);
        uint64_t whr = *reinterpret_cast<const uint64_t*>(&sWh[c * SW_STRIDE + k]);
        uint64_t whz = *reinterpret_cast<const uint64_t*>(&sWh[(64 + c) * SW_STRIDE + k]);
        uint64_t whn = *reinterpret_cast<const uint64_t*>(&sWh[(128 + c) * SW_STRIDE + k]);
#pragma unroll
        for (int i = 0; i < 8; i++) {
            uint64_t m2 = *reinterpret_cast<const uint64_t*>(&sIn[(r0 + i) * 64 + k]);
            uint64_t h2 = *reinterpret_cast<const uint64_t*>(&sHh[(r0 + i) * 64 + k]);
            air[i] = fma2_(wir, m2, air[i]);
            aiz[i] = fma2_(wiz, m2, aiz[i]);
            ain[i] = fma2_(win, m2, ain[i]);
            ahr[i] = fma2_(whr, h2, ahr[i]);
            ahz[i] = fma2_(whz, h2, ahz[i]);
            ahn[i] = fma2_(whn, h2, ahn[i]);
        }
    }
    float bir = sBi[c], biz = sBi[64 + c], bin = sBi[128 + c];
    float bhr = sBh[c], bhz = sBh[64 + c], bhn = sBh[128 + c];
#pragma unroll
    for (int i = 0; i < 8; i++) {
        float rr = sigmoidf_(hsum2_(air[i]) + bir + hsum2_(ahr[i]) + bhr);
        float zz = sigmoidf_(hsum2_(aiz[i]) + biz + hsum2_(ahz[i]) + bhz);
        float ng = tanhf(hsum2_(ain[i]) + bin + rr * (hsum2_(ahn[i]) + bhn));
        hout[i] = (1.f - zz) * ng + zz * sHh[(r0 + i) * 64 + c];
    }
}

__global__ void __launch_bounds__(256, 1)
gru_kernel(const float* __restrict__ Wi_n, const float* __restrict__ bi_n,
           const float* __restrict__ Wh_n, const float* __restrict__ bh_n,
           const float* __restrict__ Wi_e, const float* __restrict__ bi_e,
           const float* __restrict__ Wh_e, const float* __restrict__ bh_e,
           const float* __restrict__ w_on, const float* __restrict__ b_on,
           const float* __restrict__ w_oe, const float* __restrict__ b_oe,
           float* __restrict__ out, int N) {
    extern __shared__ float sm[];
    float* sWiN = sm + OFF_WIN;
    float* sWhN = sm + OFF_WHN;
    float* sWiE = sm + OFF_WIE;
    float* sWhE = sm + OFF_WHE;
    float* sBiN = sm + OFF_BIN;
    float* sBhN = sm + OFF_BHN;
    float* sBiE = sm + OFF_BIE;
    float* sBhE = sm + OFF_BHE;
    float* sM = sm + OFF_M;
    float* sH = sm + OFF_H;
    float* sE = sm + OFF_E;
    float* sY = sm + OFF_Y;

    int tid = threadIdx.x;
    int c = tid & 63, rg = tid >> 6;
    int lane = tid & 31, warp = tid >> 5;

    for (int idx = tid; idx < 192 * 64; idx += 256) {
        int j = idx >> 6, k = idx & 63;
        int p = j * SW_STRIDE + k;
        sWiN[p] = Wi_n[idx];
        sWhN[p] = Wh_n[idx];
        sWiE[p] = Wi_e[idx];
        sWhE[p] = Wh_e[idx];
    }
    if (tid < 192) {
        sBiN[tid] = bi_n[tid]; sBhN[tid] = bh_n[tid];
        sBiE[tid] = bi_e[tid]; sBhE[tid] = bh_e[tid];
    }
    float won = w_on[c], woe = w_oe[c];
    float bon = b_on[0], boe = b_oe[0];

    float* outS = out;
    float* outY = out + N;
    float* outH = out + 2 * (size_t)N;

    const float4* mn4 = reinterpret_cast<const float4*>(g_mn);
    const float4* h4g = reinterpret_cast<const float4*>(g_h);
    const float4* me4 = reinterpret_cast<const float4*>(g_me);
    float4* sM4 = reinterpret_cast<float4*>(sM);
    float4* sH4 = reinterpret_cast<float4*>(sH);
    float4* sE4 = reinterpret_cast<float4*>(sE);

    int ntiles = (N + 31) / 32;
    for (int t = blockIdx.x; t < ntiles; t += gridDim.x) {
        int base = t * 32;
        __syncthreads();  // protect tile smem from previous iteration
        for (int idx = tid; idx < 32 * 16; idx += 256) {
            int r = idx >> 4, k4 = idx & 15;
            int gr = base + r;
            float4 z = make_float4(0.f, 0.f, 0.f, 0.f);
            size_t off = (size_t)gr * 16 + k4;
            bool ok = gr < N;
            sM4[idx] = ok ? mn4[off] : z;
            sH4[idx] = ok ? h4g[off] : z;
            sE4[idx] = ok ? me4[off] : z;
        }
        __syncthreads();

        int r0 = rg * 8;
        float hnode[8], hedge[8];
        gru_pass(sWiN, sWhN, sBiN, sBhN, sM, sH, r0, c, hnode);
        gru_pass(sWiE, sWhE, sBiE, sBhE, sE, sH, r0, c, hedge);

        float yp[8];
#pragma unroll
        for (int i = 0; i < 8; i++) {
            int gr = base + r0 + i;
            float dnv = 0.f, dev = 0.f;
            if (gr < N) { dnv = g_dn[gr]; dev = g_de[gr]; }
            float ho = dnv * hnode[i] + dev * hedge[i];
            if (gr < N) outH[(size_t)gr * 64 + c] = ho;
            yp[i] = ho * (dnv * won + dev * woe);
        }
#pragma unroll
        for (int i = 0; i < 8; i++) {
#pragma unroll
            for (int o = 16; o > 0; o >>= 1)
                yp[i] += __shfl_xor_sync(0xffffffffu, yp[i], o);
        }
        if (lane == 0) {
#pragma unroll
            for (int i = 0; i < 8; i++) sY[warp * 8 + i] = yp[i];
        }
        __syncthreads();
        if (tid < 32) {
            int gr = base + tid;
            if (gr < N) {
                int g2 = tid >> 3, i = tid & 7;
                float v = sY[(2 * g2) * 8 + i] + sY[(2 * g2 + 1) * 8 + i];
                float dnv = g_dn[gr], dev = g_de[gr];
                float yv = v + dnv * bon + dev * boe;
                outY[gr] = yv;
                outS[gr] = sigmoidf_(yv);
            }
        }
    }
}

// ---------------------------------------------------------------------------
extern "C" void kernel_launch(void* const* d_in, const int* in_sizes, int n_in,
                              void* d_out, int out_size) {
    const float* x     = (const float*)d_in[0];
    const float* h_in  = (const float*)d_in[1];
    const int*   nrows = (const int*)d_in[2];
    const int*   ncols = (const int*)d_in[3];
    const float* nvals = (const float*)d_in[4];
    const int*   erows = (const int*)d_in[5];
    const int*   ecols = (const int*)d_in[6];
    const float* evals = (const float*)d_in[7];
    const float* W1    = (const float*)d_in[8];
    const float* b1    = (const float*)d_in[9];
    const float* gamma = (const float*)d_in[10];
    const float* beta  = (const float*)d_in[11];
    const float* W2    = (const float*)d_in[12];
    const float* b2    = (const float*)d_in[13];
    const float* Wi_n  = (const float*)d_in[14];
    const float* bi_n  = (const float*)d_in[15];
    const float* Wh_n  = (const float*)d_in[16];
    const float* bh_n  = (const float*)d_in[17];
    const float* Wi_e  = (const float*)d_in[18];
    const float* bi_e  = (const float*)d_in[19];
    const float* Wh_e  = (const float*)d_in[20];
    const float* bh_e  = (const float*)d_in[21];
    const float* w_on  = (const float*)d_in[22];
    const float* b_on  = (const float*)d_in[23];
    const float* w_oe  = (const float*)d_in[24];
    const float* b_oe  = (const float*)d_in[25];

    int Nnew = in_sizes[0] / NH;
    int Nold = in_sizes[1] / NH;
    int N = Nnew + Nold;
    int nnz_n = in_sizes[2];
    int nnz_e = in_sizes[5];
    if (N > MAXN || Nnew > MAXNEW) return;

    float* out = (float*)d_out;

    cudaFuncSetAttribute(gru_kernel, cudaFuncAttributeMaxDynamicSharedMemorySize, SMEM_BYTES);

    // 1. zero scratch + copy h_in
    prep_kernel<<<2048, 256>>>(h_in, N, Nold);
    // 2. diagonal extraction
    diag_kernel<<<1024, 256>>>(nrows, ncols, nvals, nnz_n, 0);
    diag_kernel<<<1024, 256>>>(erows, ecols, evals, nnz_e, 1);
    // 3. input transform
    int tblocks = (Nnew + 31) / 32;
    t1_kernel<<<tblocks, 256>>>(x, W1, b1, Nnew);
    stats_kernel<<<1, 64>>>(gamma, beta, Nnew);
    t2_kernel<<<tblocks, 256>>>(W2, b2, Nnew, Nold);
    // 4. sparse message passing (16 threads/edge, vector red)
    spmm_kernel<<<8192, 256>>>(nrows, ncols, nvals, nnz_n, 0);
    spmm_kernel<<<8192, 256>>>(erows, ecols, evals, nnz_e, 1);
    // 5. fused GRU + masking + heads
    gru_kernel<<<148, 256, SMEM_BYTES>>>(Wi_n, bi_n, Wh_n, bh_n,
                                         Wi_e, bi_e, Wh_e, bh_e,
                                         w_on, b_on, w_oe, b_oe, out, N);
    (void)n_in; (void)out_size;
}